// round 1
// baseline (speedup 1.0000x reference)
#include <cuda_runtime.h>

#define NN 100000
#define NE 600000
#define NV 50000
#define DIM 128
#define NNZ (NE + NN)
#define NB_SCAN ((NN + 1023) / 1024)

// ---------------- scratch (static device globals; no allocation) ----------
__device__ int   g_deg[NN];
__device__ int   g_rowptr[NN + 1];
__device__ int   g_cursor[NN];
__device__ int   g_bsum[128];
__device__ int   g_boff[128];
__device__ int   g_col[NNZ];
__device__ float g_dinv[NN];
__device__ float g_embW[(size_t)NV * DIM];   // emb @ W1   (25.6 MB)
__device__ float g_agg [(size_t)NN * DIM];   // layer-1 output (51.2 MB)
__device__ float g_hw  [(size_t)NN * DIM];   // layer-2 pre-agg (51.2 MB)

// ---------------- degree / CSR build ---------------------------------------
__global__ void k_init_deg() {
    int i = blockIdx.x * blockDim.x + threadIdx.x;
    if (i < NN) g_deg[i] = 1;                // self-loop
}

__global__ void k_count_deg(const int* __restrict__ dst) {
    int e = blockIdx.x * blockDim.x + threadIdx.x;
    if (e < NE) atomicAdd(&g_deg[dst[e]], 1);
}

__global__ void k_scan_block() {
    __shared__ int s[1024];
    int tid = threadIdx.x;
    int i = blockIdx.x * 1024 + tid;
    int v = (i < NN) ? g_deg[i] : 0;
    s[tid] = v;
    __syncthreads();
    #pragma unroll
    for (int off = 1; off < 1024; off <<= 1) {
        int t = (tid >= off) ? s[tid - off] : 0;
        __syncthreads();
        s[tid] += t;
        __syncthreads();
    }
    if (i < NN) g_rowptr[i + 1] = s[tid];    // block-local inclusive
    if (tid == 1023) g_bsum[blockIdx.x] = s[1023];
}

__global__ void k_scan_top(int nb) {
    if (threadIdx.x == 0) {
        int acc = 0;
        for (int b = 0; b < nb; b++) { g_boff[b] = acc; acc += g_bsum[b]; }
        g_rowptr[0] = 0;
    }
}

__global__ void k_scan_add() {
    int i = blockIdx.x * 1024 + threadIdx.x;
    if (i < NN) g_rowptr[i + 1] += g_boff[blockIdx.x];
}

__global__ void k_fill_init() {
    int i = blockIdx.x * blockDim.x + threadIdx.x;
    if (i < NN) {
        int base = g_rowptr[i];
        g_col[base] = i;                     // self-loop entry first
        g_cursor[i] = base + 1;
        g_dinv[i] = rsqrtf((float)g_deg[i]);
    }
}

__global__ void k_fill_edges(const int* __restrict__ src, const int* __restrict__ dst) {
    int e = blockIdx.x * blockDim.x + threadIdx.x;
    if (e < NE) {
        int pos = atomicAdd(&g_cursor[dst[e]], 1);
        g_col[pos] = src[e];
    }
}

// ---------------- dense GEMM: C[M,128] = A[M,128] @ W[128,128] -------------
// 64 rows / block, 256 threads, 8x4 register tile per thread.
// A staged in smem (broadcast reads); W streamed through L1 (64 KB resident).
__global__ __launch_bounds__(256) void k_gemm128(
    const float* __restrict__ A, const float* __restrict__ W,
    float* __restrict__ C, int M)
{
    __shared__ float sA[64 * DIM];
    int tid = threadIdx.x;
    int row0 = blockIdx.x * 64;
    int rows_left = M - row0;

    const float4* Av = (const float4*)(A + (size_t)row0 * DIM);
    float4* sAv = (float4*)sA;
    #pragma unroll
    for (int i = 0; i < 8; i++) {
        int idx = tid + i * 256;
        int r = idx >> 5;                    // 32 float4 per row
        float4 v = make_float4(0.f, 0.f, 0.f, 0.f);
        if (r < rows_left) v = Av[idx];
        sAv[idx] = v;
    }
    __syncthreads();

    int lane = tid & 31;
    int ty   = tid >> 5;
    int r0   = ty * 8;
    int c0   = lane * 4;
    float acc[8][4];
    #pragma unroll
    for (int r = 0; r < 8; r++)
        acc[r][0] = acc[r][1] = acc[r][2] = acc[r][3] = 0.f;

    #pragma unroll 8
    for (int k = 0; k < DIM; k++) {
        float4 w = __ldg((const float4*)(W + k * DIM + c0));
        #pragma unroll
        for (int r = 0; r < 8; r++) {
            float a = sA[(r0 + r) * DIM + k];  // warp-uniform broadcast
            acc[r][0] = fmaf(a, w.x, acc[r][0]);
            acc[r][1] = fmaf(a, w.y, acc[r][1]);
            acc[r][2] = fmaf(a, w.z, acc[r][2]);
            acc[r][3] = fmaf(a, w.w, acc[r][3]);
        }
    }

    #pragma unroll
    for (int r = 0; r < 8; r++) {
        int rr = row0 + r0 + r;
        if (rr < M)
            *(float4*)(C + (size_t)rr * DIM + c0) =
                make_float4(acc[r][0], acc[r][1], acc[r][2], acc[r][3]);
    }
}

// ---------------- SpMM gather: out[i] = relu(dinv[i]*Σ dinv[j]*feat[row(j)] + b)
// One warp per node; lane handles 4 contiguous columns (float4, coalesced 512B rows).
template<bool LAYER1>
__global__ __launch_bounds__(256) void k_spmm(
    const float* __restrict__ feat, const int* __restrict__ x,
    const float* __restrict__ bias, float* __restrict__ out)
{
    int node = (int)((blockIdx.x * blockDim.x + threadIdx.x) >> 5);
    if (node >= NN) return;
    int lane = threadIdx.x & 31;

    int start = g_rowptr[node];
    int end   = g_rowptr[node + 1];
    const float4* f4 = (const float4*)feat;

    float ax = 0.f, ay = 0.f, az = 0.f, aw = 0.f;
    int k = start;
    for (; k + 1 < end; k += 2) {            // 2-way ILP on the gather chain
        int c0 = g_col[k];
        int c1 = g_col[k + 1];
        float w0 = g_dinv[c0];
        float w1 = g_dinv[c1];
        int r0 = LAYER1 ? x[c0] : c0;
        int r1 = LAYER1 ? x[c1] : c1;
        float4 v0 = f4[(size_t)r0 * 32 + lane];
        float4 v1 = f4[(size_t)r1 * 32 + lane];
        ax = fmaf(w0, v0.x, ax); ay = fmaf(w0, v0.y, ay);
        az = fmaf(w0, v0.z, az); aw = fmaf(w0, v0.w, aw);
        ax = fmaf(w1, v1.x, ax); ay = fmaf(w1, v1.y, ay);
        az = fmaf(w1, v1.z, az); aw = fmaf(w1, v1.w, aw);
    }
    if (k < end) {
        int c = g_col[k];
        float w = g_dinv[c];
        int r = LAYER1 ? x[c] : c;
        float4 v = f4[(size_t)r * 32 + lane];
        ax = fmaf(w, v.x, ax); ay = fmaf(w, v.y, ay);
        az = fmaf(w, v.z, az); aw = fmaf(w, v.w, aw);
    }

    float di = g_dinv[node];
    float4 b = __ldg((const float4*)bias + lane);
    float4 o;
    o.x = fmaxf(fmaf(di, ax, b.x), 0.f);
    o.y = fmaxf(fmaf(di, ay, b.y), 0.f);
    o.z = fmaxf(fmaf(di, az, b.z), 0.f);
    o.w = fmaxf(fmaf(di, aw, b.w), 0.f);
    ((float4*)out)[(size_t)node * 32 + lane] = o;
}

// ---------------- launch ----------------------------------------------------
extern "C" void kernel_launch(void* const* d_in, const int* in_sizes, int n_in,
                              void* d_out, int out_size) {
    const int*   x   = (const int*)d_in[0];
    const int*   src = (const int*)d_in[1];          // edge_index[0]
    const int*   dst = src + NE;                     // edge_index[1]
    const float* emb = (const float*)d_in[2];
    const float* W1  = (const float*)d_in[3];
    const float* b1  = (const float*)d_in[4];
    const float* W2  = (const float*)d_in[5];
    const float* b2  = (const float*)d_in[6];
    float*       out = (float*)d_out;

    float *p_embW, *p_agg, *p_hw;
    cudaGetSymbolAddress((void**)&p_embW, g_embW);
    cudaGetSymbolAddress((void**)&p_agg,  g_agg);
    cudaGetSymbolAddress((void**)&p_hw,   g_hw);

    // CSR build (by dst, self-loops included)
    k_init_deg  <<<(NN + 255) / 256, 256>>>();
    k_count_deg <<<(NE + 255) / 256, 256>>>(dst);
    k_scan_block<<<NB_SCAN, 1024>>>();
    k_scan_top  <<<1, 32>>>(NB_SCAN);
    k_scan_add  <<<NB_SCAN, 1024>>>();
    k_fill_init <<<(NN + 255) / 256, 256>>>();
    k_fill_edges<<<(NE + 255) / 256, 256>>>(src, dst);

    // Layer 1: embW = emb @ W1 (vocab-sized GEMM), then gathered aggregation
    k_gemm128<<<(NV + 63) / 64, 256>>>(emb, W1, p_embW, NV);
    k_spmm<true><<<(NN + 7) / 8, 256>>>(p_embW, x, b1, p_agg);

    // Layer 2: hw = agg @ W2, then aggregation into d_out
    k_gemm128<<<(NN + 63) / 64, 256>>>(p_agg, W2, p_hw, NN);
    k_spmm<false><<<(NN + 7) / 8, 256>>>(p_hw, x, b2, out);
}